// round 1
// baseline (speedup 1.0000x reference)
#include <cuda_runtime.h>

// Problem shape (fixed by the dataset): B=8, N=1024, C=128, H=W=512.
static constexpr int  Bc = 8;
static constexpr int  Nc = 1024;
static constexpr int  Cc = 128;
static constexpr int  Hc = 512;
static constexpr int  Wc = 512;
static constexpr long long PIX = (long long)Bc * Hc * Wc;   // 2,097,152 pixels
static constexpr int  C4 = Cc / 4;                          // 32 float4 per pixel
static constexpr int  HW_SHIFT = 18;                        // H*W = 2^18

// One warp per pixel. Lane l moves float4 chunk l of the 128-float feature row.
// - slic load: all lanes hit the same 4B word -> single-sector broadcast.
// - feat load: 512B contiguous row, L2-resident (4MB table).
// - out store: 512B fully-coalesced STG.128 burst per warp.
__global__ void __launch_bounds__(256)
convert2image_gather(const float4* __restrict__ feat,   // [B, N, C/4]
                     const int*    __restrict__ slic,   // [B*H*W]
                     float4*       __restrict__ out)    // [B*H*W, C/4]
{
    long long tid  = (long long)blockIdx.x * blockDim.x + threadIdx.x;
    long long pix  = tid >> 5;
    int       lane = (int)(tid & 31);

    if (pix >= PIX) return;

    int b   = (int)(pix >> HW_SHIFT);
    int idx = __ldg(slic + pix) - 1;          // labels are 1-indexed

    float4 v = make_float4(0.f, 0.f, 0.f, 0.f);
    if ((unsigned)idx < (unsigned)Nc) {
        v = __ldg(feat + ((long long)b * Nc + idx) * C4 + lane);
    }
    out[(pix << 5) + lane] = v;
}

extern "C" void kernel_launch(void* const* d_in, const int* in_sizes, int n_in,
                              void* d_out, int out_size)
{
    const float4* feat = (const float4*)d_in[0];   // graph_lstm_output, fp32 [B,N,C]
    const int*    slic = (const int*)d_in[1];      // slic_output, int32 [B,H,W,1]
    float4*       out  = (float4*)d_out;           // fp32 [B,H,W,C]

    const long long total_threads = PIX * 32;      // 67,108,864
    const int  threads = 256;
    const unsigned blocks = (unsigned)((total_threads + threads - 1) / threads); // 262,144

    convert2image_gather<<<blocks, threads>>>(feat, slic, out);
}

// round 2
// speedup vs baseline: 1.8343x; 1.8343x over previous
#include <cuda_runtime.h>

// Problem shape (fixed by the dataset): B=8, N=1024, C=128, H=W=512.
static constexpr int  Nc = 1024;
static constexpr int  C4 = 32;            // 128 floats = 32 float4 per pixel
static constexpr int  HW_SHIFT = 18;      // H*W = 2^18 pixels per batch image
static constexpr long long PIX = 8LL << HW_SHIFT;   // 2,097,152 pixels
static constexpr int  P = 4;              // pixels per warp (MLP factor)

// One warp handles P=4 consecutive pixels. Lane l owns float4-chunk l of each
// pixel's 128-float feature row.
//  - index load: lanes 0..3 load 4 consecutive int32 (1 sector), shfl-broadcast
//  - gather: 4 INDEPENDENT LDG.128 per thread (MLP=4), rows are L2-resident
//  - store: 4 coalesced 512B STG.128 bursts, streaming hint (__stcs) since
//    output is write-once; keeps the 4MB feature table resident in L2.
__global__ void __launch_bounds__(256)
convert2image_gather4(const float4* __restrict__ feat,   // [B, N, C/4]
                      const int*    __restrict__ slic,   // [B*H*W]
                      float4*       __restrict__ out)    // [B*H*W, C/4]
{
    const long long warp_gid = (long long)blockIdx.x * (blockDim.x >> 5)
                             + (threadIdx.x >> 5);
    const long long pix0 = warp_gid * P;
    const int lane = threadIdx.x & 31;

    if (pix0 >= PIX) return;

    // All P pixels of a warp lie in the same batch image (P divides H*W).
    const int b = (int)(pix0 >> HW_SHIFT);
    const float4* __restrict__ fb = feat + ((long long)b * Nc) * C4;

    // Lanes 0..P-1 fetch the P segment labels (one 16B sector total).
    int myidx = 0;
    if (lane < P) myidx = __ldg(slic + pix0 + lane) - 1;   // labels 1-indexed

    float4 v[P];
    #pragma unroll
    for (int p = 0; p < P; p++) {
        const int idx = __shfl_sync(0xffffffffu, myidx, p);
        v[p] = make_float4(0.f, 0.f, 0.f, 0.f);
        if ((unsigned)idx < (unsigned)Nc) {
            v[p] = __ldg(fb + (long long)idx * C4 + lane);  // independent -> MLP=P
        }
    }

    float4* __restrict__ o = out + (pix0 << 5) + lane;
    #pragma unroll
    for (int p = 0; p < P; p++) {
        __stcs(o + (p << 5), v[p]);    // streaming: write-once, evict-first
    }
}

extern "C" void kernel_launch(void* const* d_in, const int* in_sizes, int n_in,
                              void* d_out, int out_size)
{
    const float4* feat = (const float4*)d_in[0];   // graph_lstm_output fp32 [B,N,C]
    const int*    slic = (const int*)d_in[1];      // slic_output int32 [B,H,W,1]
    float4*       out  = (float4*)d_out;           // fp32 [B,H,W,C]

    const int threads = 256;                        // 8 warps -> 32 pixels/block
    const long long pixels_per_block = (threads / 32) * P;
    const unsigned blocks = (unsigned)((PIX + pixels_per_block - 1) / pixels_per_block); // 65,536

    convert2image_gather4<<<blocks, threads>>>(feat, slic, out);
}